// round 1
// baseline (speedup 1.0000x reference)
#include <cuda_runtime.h>

// VQVAE quantization:
//   laten   : (B=32, D=64, H=32, W=32) fp32
//   codebook: (K=2048, D=64) fp32
// Outputs (concatenated, fp32):
//   idx   : (B, H, W) = 32768 values (argmin index, cast to float)
//   quant : (B, D, H, W) = 2097152 values (codebook gather, channel-first)

#define NB 32
#define ND 64
#define NH 32
#define NW 32
#define NK 2048
#define N_POINTS (NB * NH * NW)      // 32768
#define N_QUANT  (NB * ND * NH * NW) // 2097152
#define HW (NH * NW)                 // 1024
#define TK 128                       // codebook tile (codes per smem tile)
#define THREADS 256

__device__ float g_esq[NK];

// --- kernel 0: per-code squared norms ---------------------------------------
__global__ void esq_kernel(const float* __restrict__ codebook) {
    int k = blockIdx.x * blockDim.x + threadIdx.x;
    if (k < NK) {
        const float4* row = (const float4*)(codebook + k * ND);
        float s = 0.f;
#pragma unroll
        for (int i = 0; i < ND / 4; i++) {
            float4 v = row[i];
            s += v.x * v.x + v.y * v.y + v.z * v.z + v.w * v.w;
        }
        g_esq[k] = s;
    }
}

// --- kernel 1: argmin + gather ----------------------------------------------
// mode bit0: write idx at out[0..N_POINTS)
// mode bit1: write quant at out[idx_off .. idx_off + N_QUANT)
__global__ void __launch_bounds__(THREADS)
vq_kernel(const float* __restrict__ laten,
          const float* __restrict__ codebook,
          float* __restrict__ out,
          int mode, int idx_off)
{
    __shared__ float s_code[TK * ND];
    __shared__ float s_esq[TK];

    const int n  = blockIdx.x * THREADS + threadIdx.x; // point id
    const int b  = n >> 10;                            // n / HW
    const int hw = n & (HW - 1);                       // n % HW

    // Load x row into registers: laten[b, d, h, w] = laten[b*ND*HW + d*HW + hw]
    // Consecutive threads -> consecutive hw -> coalesced per d.
    const float* xp = laten + (size_t)b * (ND * HW) + hw;
    float x[ND];
#pragma unroll
    for (int d = 0; d < ND; d++) x[d] = xp[d * HW];

    float best  = 3.4e38f;
    int   bestk = 0;

    for (int kt = 0; kt < NK; kt += TK) {
        __syncthreads();
        // Cooperative tile load: TK*ND floats = TK*16 float4, coalesced.
        const float4* src = (const float4*)(codebook + kt * ND);
        float4* dst = (float4*)s_code;
#pragma unroll
        for (int i = threadIdx.x; i < TK * ND / 4; i += THREADS)
            dst[i] = src[i];
        if (threadIdx.x < TK) s_esq[threadIdx.x] = g_esq[kt + threadIdx.x];
        __syncthreads();

#pragma unroll 1
        for (int kk = 0; kk < TK; kk += 2) {
            const float4* c0 = (const float4*)(s_code + kk * ND);
            const float4* c1 = (const float4*)(s_code + kk * ND + ND);
            // 8 independent FFMA chains (depth 16) for ILP.
            float a00 = 0.f, a01 = 0.f, a02 = 0.f, a03 = 0.f;
            float a10 = 0.f, a11 = 0.f, a12 = 0.f, a13 = 0.f;
#pragma unroll
            for (int i = 0; i < ND / 4; i++) {
                float4 v0 = c0[i];
                a00 = fmaf(x[4 * i + 0], v0.x, a00);
                a01 = fmaf(x[4 * i + 1], v0.y, a01);
                a02 = fmaf(x[4 * i + 2], v0.z, a02);
                a03 = fmaf(x[4 * i + 3], v0.w, a03);
                float4 v1 = c1[i];
                a10 = fmaf(x[4 * i + 0], v1.x, a10);
                a11 = fmaf(x[4 * i + 1], v1.y, a11);
                a12 = fmaf(x[4 * i + 2], v1.z, a12);
                a13 = fmaf(x[4 * i + 3], v1.w, a13);
            }
            float dot0 = (a00 + a01) + (a02 + a03);
            float dot1 = (a10 + a11) + (a12 + a13);
            // score = e_sq - 2*dot  (x_sq and /D dropped: monotone in argmin)
            float s0 = fmaf(-2.f, dot0, s_esq[kk]);
            float s1 = fmaf(-2.f, dot1, s_esq[kk + 1]);
            // strict < keeps first index on ties (matches jnp.argmin)
            if (s0 < best) { best = s0; bestk = kt + kk; }
            if (s1 < best) { best = s1; bestk = kt + kk + 1; }
        }
    }

    // --- outputs ---
    if (mode & 1)
        out[n] = (float)bestk;

    if (mode & 2) {
        float* outq = out + idx_off;
        const float* cb = codebook + bestk * ND;
#pragma unroll
        for (int d = 0; d < ND; d++)
            outq[(size_t)b * (ND * HW) + d * HW + hw] = __ldg(&cb[d]);
    }
}

extern "C" void kernel_launch(void* const* d_in, const int* in_sizes, int n_in,
                              void* d_out, int out_size) {
    const float* laten    = (const float*)d_in[0];
    const float* codebook = (const float*)d_in[1];
    float* out = (float*)d_out;

    // Defensive output-layout handling based on out_size.
    int mode, idx_off;
    if (out_size == N_POINTS + N_QUANT) { mode = 3; idx_off = N_POINTS; }
    else if (out_size == N_QUANT)       { mode = 2; idx_off = 0;        }
    else                                { mode = 1; idx_off = 0;        }

    esq_kernel<<<(NK + 255) / 256, 256>>>(codebook);
    vq_kernel<<<N_POINTS / THREADS, THREADS>>>(laten, codebook, out, mode, idx_off);
}

// round 8
// speedup vs baseline: 1.6057x; 1.6057x over previous
#include <cuda_runtime.h>
#include <cuda_bf16.h>
#include <cstdint>

// ============================================================================
// VQVAE quantization: split-bf16 mma.sync GEMM + top-2 margin + exact rescue.
//   laten   : (B=32, D=64, H=32, W=32) fp32
//   codebook: (K=2048, D=64) fp32
// Output (fp32): [ idx (32768) | quant (2097152, channel-first) ]
// ============================================================================

#define NB 32
#define ND 64
#define NH 32
#define NW 32
#define NK 2048
#define HW (NH * NW)                  // 1024
#define N_POINTS (NB * HW)            // 32768
#define N_QUANT  (NB * ND * HW)       // 2097152
#define KE 192                        // expanded K: [xh | xh | xl] x [ch | cl | ch]
#define TM 128                        // points per CTA
#define TN 64                         // codes per N-tile
#define NTILES (NK / TN)              // 32
#define KSTEPS (KE / 16)              // 12
#define ROWB 400                      // padded smem row bytes (25*16, 25%8==1)
#define MARGIN 0.08f

// smem layout (bytes)
#define SM_A    0                     // 128 * 400 = 51200
#define SM_B    51200                 // 2 buffers * 64*400 = 51200
#define SM_ESQ  102400                // 2048 * 4 = 8192
#define SM_SIZE 110592

// ---- device scratch ---------------------------------------------------------
__device__ __align__(16) __nv_bfloat16 g_B[NK * KE];   // 0.79 MB, L2-resident
__device__ __align__(16) float g_esq[NK];
__device__ float g_b1[N_POINTS];
__device__ float g_b2[N_POINTS];
__device__ int   g_bk[N_POINTS];
__device__ int   g_rescan[N_POINTS];
__device__ int   g_rcount;

// ---- helpers ----------------------------------------------------------------
__device__ __forceinline__ uint32_t smem_u32(const void* p) {
    uint32_t a;
    asm("{ .reg .u64 t; cvta.to.shared.u64 t, %1; cvt.u32.u64 %0, t; }"
        : "=r"(a) : "l"(p));
    return a;
}
#define CP_ASYNC16(s, g) \
    asm volatile("cp.async.cg.shared.global [%0], [%1], 16;" :: "r"(s), "l"(g))
#define CP_COMMIT() asm volatile("cp.async.commit_group;" ::: "memory")
#define CP_WAIT(n)  asm volatile("cp.async.wait_group %0;" :: "n"(n) : "memory")

#define LDSM_X4(r0, r1, r2, r3, a)                                             \
    asm volatile("ldmatrix.sync.aligned.m8n8.x4.shared.b16 {%0,%1,%2,%3}, [%4];" \
                 : "=r"(r0), "=r"(r1), "=r"(r2), "=r"(r3) : "r"(a))

#define MMA_BF16(c, a, b0, b1)                                                 \
    asm volatile("mma.sync.aligned.m16n8k16.row.col.f32.bf16.bf16.f32 "        \
                 "{%0,%1,%2,%3}, {%4,%5,%6,%7}, {%8,%9}, {%0,%1,%2,%3};"       \
                 : "+f"((c)[0]), "+f"((c)[1]), "+f"((c)[2]), "+f"((c)[3])      \
                 : "r"((a)[0]), "r"((a)[1]), "r"((a)[2]), "r"((a)[3]),         \
                   "r"(b0), "r"(b1))

// ---- kernel: zero rescan counter -------------------------------------------
__global__ void zero_kernel() { g_rcount = 0; }

// ---- kernel: build B (2048 x 192 bf16, row-major) + exact esq --------------
__global__ void build_B_kernel(const float* __restrict__ codebook) {
    int k = blockIdx.x * blockDim.x + threadIdx.x;
    if (k >= NK) return;
    const float4* row = (const float4*)(codebook + k * ND);
    __nv_bfloat16* out = g_B + (size_t)k * KE;
    float s = 0.f;
#pragma unroll
    for (int i = 0; i < ND / 4; i++) {
        float4 v = row[i];
        s += v.x * v.x + v.y * v.y + v.z * v.z + v.w * v.w;
        float f[4] = {v.x, v.y, v.z, v.w};
#pragma unroll
        for (int j = 0; j < 4; j++) {
            int d = 4 * i + j;
            __nv_bfloat16 hi = __float2bfloat16(f[j]);
            __nv_bfloat16 lo = __float2bfloat16(f[j] - __bfloat162float(hi));
            out[d]       = hi;   // seg0: ch (x xh)
            out[64 + d]  = lo;   // seg1: cl (x xh)
            out[128 + d] = hi;   // seg2: ch (x xl)
        }
    }
    g_esq[k] = s;
}

// ---- main kernel: fused A-convert + GEMM + top-2 argmin --------------------
__global__ void __launch_bounds__(256, 2)
gemm_argmin_kernel(const float* __restrict__ laten) {
    extern __shared__ char smem[];
    const uint32_t sb = smem_u32(smem);
    const int tid  = threadIdx.x;
    const int lane = tid & 31;
    const int wid  = tid >> 5;
    const int warp_m = (wid & 3) * 32;   // 4 m-warps
    const int warp_n = (wid >> 2) * 32;  // 2 n-warps

    const int n0  = blockIdx.x * TM;
    const int b   = n0 >> 10;
    const int hw0 = n0 & (HW - 1);

    // -- prologue: B tiles 0,1 via cp.async (2 groups) --
#pragma unroll 1
    for (int t = 0; t < 2; t++) {
        const char* gsrc = (const char*)(g_B + (size_t)t * TN * KE);
#pragma unroll
        for (int i = tid; i < TN * 24; i += 256) {
            int row = i / 24, c = i % 24;
            CP_ASYNC16(sb + SM_B + t * 25600 + row * ROWB + c * 16,
                       gsrc + row * (KE * 2) + c * 16);
        }
        CP_COMMIT();
    }

    // -- A convert: laten -> split-bf16 padded smem tile --
    {
        const int p  = tid & 127;
        const int db = tid >> 7;
        const float* lp = laten + (size_t)b * (ND * HW) + hw0 + p;
#pragma unroll
        for (int i = 0; i < 32; i++) {
            int d = 2 * i + db;
            float f = lp[d * HW];
            __nv_bfloat16 hi = __float2bfloat16(f);
            __nv_bfloat16 lo = __float2bfloat16(f - __bfloat162float(hi));
            unsigned short hb = __bfloat16_as_ushort(hi);
            unsigned short lb = __bfloat16_as_ushort(lo);
            *(unsigned short*)(smem + SM_A + p * ROWB + d * 2)       = hb;
            *(unsigned short*)(smem + SM_A + p * ROWB + 128 + d * 2) = hb;
            *(unsigned short*)(smem + SM_A + p * ROWB + 256 + d * 2) = lb;
        }
    }
    // -- esq -> smem --
#pragma unroll
    for (int i = tid; i < NK / 4; i += 256)
        ((float4*)(smem + SM_ESQ))[i] = ((const float4*)g_esq)[i];

    CP_WAIT(1);
    __syncthreads();

    // ldmatrix lane base addresses (mat = lane>>3)
    // A x4: mats = {r0-7,k0},{r8-15,k0},{r0-7,k1},{r8-15,k1}
    const uint32_t a_base = sb + SM_A
        + (uint32_t)(warp_m + ((lane >> 3) & 1) * 8 + (lane & 7)) * ROWB
        + (uint32_t)(lane >> 4) * 16;
    // B x4: mats = {n0-7,k0},{n0-7,k1},{n8-15,k0},{n8-15,k1}
    const uint32_t b_base = sb + SM_B
        + (uint32_t)(warp_n + (lane >> 4) * 8 + (lane & 7)) * ROWB
        + (uint32_t)((lane >> 3) & 1) * 16;

    // top-2 state: 4 row-slots (mi*2 + rowhalf)
    float b1v[4] = {3.4e38f, 3.4e38f, 3.4e38f, 3.4e38f};
    float b2v[4] = {3.4e38f, 3.4e38f, 3.4e38f, 3.4e38f};
    int   bkv[4] = {0, 0, 0, 0};

#pragma unroll 1
    for (int nt = 0; nt < NTILES; nt++) {
        const uint32_t bB = b_base + (nt & 1) * 25600;
        float acc[2][4][4];
#pragma unroll
        for (int mi = 0; mi < 2; mi++)
#pragma unroll
            for (int ni = 0; ni < 4; ni++)
#pragma unroll
                for (int q = 0; q < 4; q++) acc[mi][ni][q] = 0.f;

#pragma unroll
        for (int s = 0; s < KSTEPS; s++) {
            uint32_t a0r[4], a1r[4], p0[4], p1[4];
            LDSM_X4(a0r[0], a0r[1], a0r[2], a0r[3], a_base + s * 32);
            LDSM_X4(a1r[0], a1r[1], a1r[2], a1r[3], a_base + 16 * ROWB + s * 32);
            LDSM_X4(p0[0], p0[1], p0[2], p0[3], bB + s * 32);
            LDSM_X4(p1[0], p1[1], p1[2], p1[3], bB + 16 * ROWB + s * 32);
            MMA_BF16(acc[0][0], a0r, p0[0], p0[1]);
            MMA_BF16(acc[0][1], a0r, p0[2], p0[3]);
            MMA_BF16(acc[0][2], a0r, p1[0], p1[1]);
            MMA_BF16(acc[0][3], a0r, p1[2], p1[3]);
            MMA_BF16(acc[1][0], a1r, p0[0], p0[1]);
            MMA_BF16(acc[1][1], a1r, p0[2], p0[3]);
            MMA_BF16(acc[1][2], a1r, p1[0], p1[1]);
            MMA_BF16(acc[1][3], a1r, p1[2], p1[3]);
        }

        // epilogue: score = esq - 2*dot, track top-2 per row-slot
        const float* es = (const float*)(smem + SM_ESQ) + nt * TN + warp_n;
#pragma unroll
        for (int ni = 0; ni < 4; ni++) {
            int cb = ni * 8 + 2 * (lane & 3);
            float2 ev = *(const float2*)(es + cb);
            int colg = nt * TN + warp_n + cb;
#pragma unroll
            for (int mi = 0; mi < 2; mi++)
#pragma unroll
                for (int h = 0; h < 2; h++) {
                    int slot = mi * 2 + h;
                    float s0 = fmaf(-2.f, acc[mi][ni][2 * h + 0], ev.x);
                    float s1 = fmaf(-2.f, acc[mi][ni][2 * h + 1], ev.y);
                    if (s0 < b1v[slot]) {
                        b2v[slot] = b1v[slot]; b1v[slot] = s0; bkv[slot] = colg;
                    } else if (s0 < b2v[slot]) b2v[slot] = s0;
                    if (s1 < b1v[slot]) {
                        b2v[slot] = b1v[slot]; b1v[slot] = s1; bkv[slot] = colg + 1;
                    } else if (s1 < b2v[slot]) b2v[slot] = s1;
                }
        }

        __syncthreads();            // all warps done reading buf (nt&1)
        if (nt + 2 < NTILES) {      // refill it with tile nt+2
            const char* gsrc = (const char*)(g_B + (size_t)(nt + 2) * TN * KE);
#pragma unroll
            for (int i = tid; i < TN * 24; i += 256) {
                int row = i / 24, c = i % 24;
                CP_ASYNC16(sb + SM_B + (nt & 1) * 25600 + row * ROWB + c * 16,
                           gsrc + row * (KE * 2) + c * 16);
            }
            CP_COMMIT();
            CP_WAIT(1);             // tile nt+1 complete
        } else {
            CP_WAIT(0);
        }
        __syncthreads();
    }

    // -- merge 1: across the 4 lanes sharing each accumulator row ------------
#pragma unroll
    for (int slot = 0; slot < 4; slot++) {
#pragma unroll
        for (int m = 1; m <= 2; m <<= 1) {
            float o1 = __shfl_xor_sync(0xffffffffu, b1v[slot], m);
            float o2 = __shfl_xor_sync(0xffffffffu, b2v[slot], m);
            int   ok = __shfl_xor_sync(0xffffffffu, bkv[slot], m);
            float nb2 = fminf(fmaxf(b1v[slot], o1), fminf(b2v[slot], o2));
            if (o1 < b1v[slot]) { b1v[slot] = o1; bkv[slot] = ok; }
            b2v[slot] = nb2;
        }
    }

    // -- merge 2: across the two n-warp groups (warp_n 0 vs 32) --------------
    // The A-tile smem region is dead after the mainloop's final barrier.
    float* cmb = (float*)(smem + SM_A);   // [TM][4] floats
    if (warp_n == 32 && (lane & 3) == 0) {
#pragma unroll
        for (int slot = 0; slot < 4; slot++) {
            int mi = slot >> 1, h = slot & 1;
            int row = warp_m + mi * 16 + h * 8 + (lane >> 2);
            cmb[row * 4 + 0] = b1v[slot];
            cmb[row * 4 + 1] = b2v[slot];
            ((int*)cmb)[row * 4 + 2] = bkv[slot];
        }
    }
    __syncthreads();
    if (warp_n == 0 && (lane & 3) == 0) {
#pragma unroll
        for (int slot = 0; slot < 4; slot++) {
            int mi = slot >> 1, h = slot & 1;
            int row = warp_m + mi * 16 + h * 8 + (lane >> 2);
            float o1 = cmb[row * 4 + 0];
            float o2 = cmb[row * 4 + 1];
            int   ok = ((int*)cmb)[row * 4 + 2];
            float m1 = fminf(b1v[slot], o1);
            float m2 = fminf(fmaxf(b1v[slot], o1), fminf(b2v[slot], o2));
            int   mk = (b1v[slot] <= o1) ? bkv[slot] : ok;
            int n = n0 + row;
            g_b1[n] = m1;
            g_b2[n] = m2;
            g_bk[n] = mk;
        }
    }
}

// ---- finalize: certain points -> outputs; uncertain -> rescan list ---------
__global__ void __launch_bounds__(256)
finalize_kernel(const float* __restrict__ codebook, float* __restrict__ out,
                int mode, int idx_off) {
    int n = blockIdx.x * 256 + threadIdx.x;
    float b1 = g_b1[n], b2 = g_b2[n];
    int bk = g_bk[n];
    if (b2 - b1 < MARGIN) {
        int slot = atomicAdd(&g_rcount, 1);
        g_rescan[slot] = n;
        return;
    }
    int b = n >> 10, hw = n & (HW - 1);
    if (mode & 1) out[n] = (float)bk;
    if (mode & 2) {
        float* oq = out + idx_off + (size_t)b * (ND * HW) + hw;
        const float* cb = codebook + bk * ND;
#pragma unroll
        for (int d = 0; d < ND; d++) oq[d * HW] = __ldg(&cb[d]);
    }
}

// ---- exact fp32 rescan for near-ties ---------------------------------------
__global__ void __launch_bounds__(256)
rescan_kernel(const float* __restrict__ laten, const float* __restrict__ codebook,
              float* __restrict__ out, int mode, int idx_off) {
    __shared__ float sx[ND];
    __shared__ float sv[256];
    __shared__ int si[256];
    int tid = threadIdx.x;
    int cnt = g_rcount;
    for (int ii = blockIdx.x; ii < cnt; ii += gridDim.x) {
        int n = g_rescan[ii];
        int b = n >> 10, hw = n & (HW - 1);
        if (tid < ND) sx[tid] = laten[(size_t)b * (ND * HW) + tid * HW + hw];
        __syncthreads();
        float best = 3.4e38f;
        int bi = 0;
        for (int k = tid; k < NK; k += 256) {
            const float4* c = (const float4*)(codebook + k * ND);
            float a0 = 0.f, a1 = 0.f, a2 = 0.f, a3 = 0.f;
#pragma unroll
            for (int i = 0; i < ND / 4; i++) {
                float4 v = c[i];
                a0 = fmaf(sx[4 * i + 0], v.x, a0);
                a1 = fmaf(sx[4 * i + 1], v.y, a1);
                a2 = fmaf(sx[4 * i + 2], v.z, a2);
                a3 = fmaf(sx[4 * i + 3], v.w, a3);
            }
            float s = fmaf(-2.f, (a0 + a1) + (a2 + a3), g_esq[k]);
            if (s < best) { best = s; bi = k; }
        }
        sv[tid] = best;
        si[tid] = bi;
        __syncthreads();
        for (int off = 128; off; off >>= 1) {
            if (tid < off) {
                float ov = sv[tid + off];
                int oi = si[tid + off];
                if (ov < sv[tid] || (ov == sv[tid] && oi < si[tid])) {
                    sv[tid] = ov;
                    si[tid] = oi;
                }
            }
            __syncthreads();
        }
        int bk = si[0];
        if ((mode & 1) && tid == 0) out[n] = (float)bk;
        if ((mode & 2) && tid < ND)
            out[idx_off + (size_t)b * (ND * HW) + tid * HW + hw] =
                codebook[bk * ND + tid];
        __syncthreads();
    }
}

// ---- host launcher ----------------------------------------------------------
extern "C" void kernel_launch(void* const* d_in, const int* in_sizes, int n_in,
                              void* d_out, int out_size) {
    const float* laten    = (const float*)d_in[0];
    const float* codebook = (const float*)d_in[1];
    float* out = (float*)d_out;

    int mode, idx_off;
    if (out_size == N_POINTS + N_QUANT) { mode = 3; idx_off = N_POINTS; }
    else if (out_size == N_QUANT)       { mode = 2; idx_off = 0;        }
    else                                { mode = 1; idx_off = 0;        }

    cudaFuncSetAttribute(gemm_argmin_kernel,
                         cudaFuncAttributeMaxDynamicSharedMemorySize, SM_SIZE);

    zero_kernel<<<1, 1>>>();
    build_B_kernel<<<NK / 128, 128>>>(codebook);
    gemm_argmin_kernel<<<N_POINTS / TM, 256, SM_SIZE>>>(laten);
    finalize_kernel<<<N_POINTS / 256, 256>>>(codebook, out, mode, idx_off);
    rescan_kernel<<<256, 256>>>(laten, codebook, out, mode, idx_off);
}

// round 11
// speedup vs baseline: 1.7452x; 1.0869x over previous
#include <cuda_runtime.h>
#include <cuda_bf16.h>
#include <cstdint>

// ============================================================================
// VQVAE quantization: split-bf16 mma.sync GEMM + top-2 margin + exact rescue.
//   laten   : (B=32, D=64, H=32, W=32) fp32
//   codebook: (K=2048, D=64) fp32
// Output (fp32): [ idx (32768) | quant (2097152, channel-first) ]
// Distances computed as 3-term split-bf16 GEMM (xh.ch + xh.cl + xl.ch),
// residual error ~1e-4; points whose top-2 gap < MARGIN are re-resolved
// exactly in fp32, so the argmin is bit-exact vs the fp32 reference.
// ============================================================================

#define NB 32
#define ND 64
#define NH 32
#define NW 32
#define NK 2048
#define HW (NH * NW)                  // 1024
#define N_POINTS (NB * HW)            // 32768
#define N_QUANT  (NB * ND * HW)       // 2097152
#define TM 128                        // points per CTA
#define TN 64                         // codes per N-tile
#define NTILES (NK / TN)              // 32
#define ROWB 272                      // smem row: 256B data + 16B pad (17%8==1)
#define BUFB (TN * ROWB)              // 17408 per B buffer
#define MARGIN 0.08f

// smem layout (bytes)
#define SM_A    0                     // 128 * 272 = 34816 (A stage, live all loop)
#define SM_B    34816                 // 2 * 17408 = 34816
#define SM_ESQ  69632                 // 2048 * 4 = 8192
#define SM_SIZE 77824

// ---- device scratch ---------------------------------------------------------
__device__ __align__(16) __nv_bfloat16 g_B[NK * 128];  // [ch(64)|cl(64)] rows
__device__ __align__(16) float g_esq[NK];
__device__ int g_rescan[N_POINTS];
__device__ int g_rcount;

// ---- helpers ----------------------------------------------------------------
__device__ __forceinline__ uint32_t smem_u32(const void* p) {
    uint32_t a;
    asm("{ .reg .u64 t; cvta.to.shared.u64 t, %1; cvt.u32.u64 %0, t; }"
        : "=r"(a) : "l"(p));
    return a;
}
#define CP_ASYNC16(s, g) \
    asm volatile("cp.async.cg.shared.global [%0], [%1], 16;" :: "r"(s), "l"(g))
#define CP_COMMIT() asm volatile("cp.async.commit_group;" ::: "memory")
#define CP_WAIT(n)  asm volatile("cp.async.wait_group %0;" :: "n"(n) : "memory")

#define LDSM_X4(r0, r1, r2, r3, a)                                             \
    asm volatile("ldmatrix.sync.aligned.m8n8.x4.shared.b16 {%0,%1,%2,%3}, [%4];" \
                 : "=r"(r0), "=r"(r1), "=r"(r2), "=r"(r3) : "r"(a))

#define MMA_BF16(c, a, b0, b1)                                                 \
    asm volatile("mma.sync.aligned.m16n8k16.row.col.f32.bf16.bf16.f32 "        \
                 "{%0,%1,%2,%3}, {%4,%5,%6,%7}, {%8,%9}, {%0,%1,%2,%3};"       \
                 : "+f"((c)[0]), "+f"((c)[1]), "+f"((c)[2]), "+f"((c)[3])      \
                 : "r"((a)[0]), "r"((a)[1]), "r"((a)[2]), "r"((a)[3]),         \
                   "r"(b0), "r"(b1))

// ---- kernel: build B ([ch|cl] rows) + exact esq + zero rescan counter ------
__global__ void build_B_kernel(const float* __restrict__ codebook) {
    int k = blockIdx.x * blockDim.x + threadIdx.x;
    if (k == 0) g_rcount = 0;
    if (k >= NK) return;
    const float4* row = (const float4*)(codebook + k * ND);
    __nv_bfloat16* out = g_B + (size_t)k * 128;
    float s = 0.f;
#pragma unroll
    for (int i = 0; i < ND / 4; i++) {
        float4 v = row[i];
        s += v.x * v.x + v.y * v.y + v.z * v.z + v.w * v.w;
        float f[4] = {v.x, v.y, v.z, v.w};
#pragma unroll
        for (int j = 0; j < 4; j++) {
            int d = 4 * i + j;
            __nv_bfloat16 hi = __float2bfloat16(f[j]);
            __nv_bfloat16 lo = __float2bfloat16(f[j] - __bfloat162float(hi));
            out[d]      = hi;   // ch
            out[64 + d] = lo;   // cl
        }
    }
    g_esq[k] = s;
}

// ---- main kernel: A-convert + GEMM + top-2 argmin + fused finalize ---------
__global__ void __launch_bounds__(256, 2)
gemm_argmin_kernel(const float* __restrict__ laten,
                   const float* __restrict__ codebook,
                   float* __restrict__ out, int mode, int idx_off) {
    extern __shared__ char smem[];
    const uint32_t sb = smem_u32(smem);
    const int tid  = threadIdx.x;
    const int lane = tid & 31;
    const int wid  = tid >> 5;
    const int warp_m = (wid & 3) * 32;   // 4 m-warps
    const int warp_n = (wid >> 2) * 32;  // 2 n-warps

    const int n0  = blockIdx.x * TM;
    const int b   = n0 >> 10;
    const int hw0 = n0 & (HW - 1);

    // -- prologue: B tiles 0,1 via cp.async (2 groups) --
#pragma unroll 1
    for (int t = 0; t < 2; t++) {
        const char* gsrc = (const char*)(g_B + (size_t)t * TN * 128);
#pragma unroll
        for (int i = tid; i < TN * 16; i += 256) {
            int row = i >> 4, c = i & 15;
            CP_ASYNC16(sb + SM_B + t * BUFB + row * ROWB + c * 16,
                       gsrc + row * 256 + c * 16);
        }
        CP_COMMIT();
    }

    // -- A convert: laten -> [xh(64)|xl(64)] bf16 rows in smem --
    {
        const int p  = tid & 127;
        const int db = tid >> 7;
        const float* lp = laten + (size_t)b * (ND * HW) + hw0 + p;
#pragma unroll
        for (int i = 0; i < 32; i++) {
            int d = 2 * i + db;
            float f = lp[d * HW];
            __nv_bfloat16 hi = __float2bfloat16(f);
            __nv_bfloat16 lo = __float2bfloat16(f - __bfloat162float(hi));
            *(unsigned short*)(smem + SM_A + p * ROWB + d * 2) =
                __bfloat16_as_ushort(hi);
            *(unsigned short*)(smem + SM_A + p * ROWB + 128 + d * 2) =
                __bfloat16_as_ushort(lo);
        }
    }
    // -- esq -> smem --
#pragma unroll
    for (int i = tid; i < NK / 4; i += 256)
        ((float4*)(smem + SM_ESQ))[i] = ((const float4*)g_esq)[i];

    __syncthreads();   // A stage + esq visible

    // ldmatrix lane base addresses
    const uint32_t a_base = sb + SM_A
        + (uint32_t)(warp_m + ((lane >> 3) & 1) * 8 + (lane & 7)) * ROWB
        + (uint32_t)(lane >> 4) * 16;
    const uint32_t b_base = sb + SM_B
        + (uint32_t)(warp_n + (lane >> 4) * 8 + (lane & 7)) * ROWB
        + (uint32_t)((lane >> 3) & 1) * 16;

    // -- hoist A-hi fragments for the whole tile loop (invariant) --
    uint32_t axh[4][2][4];
#pragma unroll
    for (int ks = 0; ks < 4; ks++) {
#pragma unroll
        for (int mi = 0; mi < 2; mi++)
            LDSM_X4(axh[ks][mi][0], axh[ks][mi][1], axh[ks][mi][2],
                    axh[ks][mi][3], a_base + mi * 16 * ROWB + ks * 32);
    }

    CP_WAIT(1);
    __syncthreads();   // B tile 0 visible

    // top-2 state: 4 row-slots (mi*2 + rowhalf)
    float b1v[4] = {3.4e38f, 3.4e38f, 3.4e38f, 3.4e38f};
    float b2v[4] = {3.4e38f, 3.4e38f, 3.4e38f, 3.4e38f};
    int   bkv[4] = {0, 0, 0, 0};

#pragma unroll 1
    for (int nt = 0; nt < NTILES; nt++) {
        const uint32_t bB = b_base + (nt & 1) * BUFB;
        float acc[2][4][4];
#pragma unroll
        for (int mi = 0; mi < 2; mi++)
#pragma unroll
            for (int ni = 0; ni < 4; ni++)
#pragma unroll
                for (int q = 0; q < 4; q++) acc[mi][ni][q] = 0.f;

        // seg0 (xh.ch) + seg2 (xl.ch): share the ch fragments
#pragma unroll
        for (int ks = 0; ks < 4; ks++) {
            uint32_t bh0[4], bh1[4], al0[4], al1[4];
            LDSM_X4(bh0[0], bh0[1], bh0[2], bh0[3], bB + ks * 32);
            LDSM_X4(bh1[0], bh1[1], bh1[2], bh1[3], bB + 16 * ROWB + ks * 32);
            LDSM_X4(al0[0], al0[1], al0[2], al0[3], a_base + 128 + ks * 32);
            LDSM_X4(al1[0], al1[1], al1[2], al1[3],
                    a_base + 16 * ROWB + 128 + ks * 32);
            MMA_BF16(acc[0][0], axh[ks][0], bh0[0], bh0[1]);
            MMA_BF16(acc[0][1], axh[ks][0], bh0[2], bh0[3]);
            MMA_BF16(acc[0][2], axh[ks][0], bh1[0], bh1[1]);
            MMA_BF16(acc[0][3], axh[ks][0], bh1[2], bh1[3]);
            MMA_BF16(acc[1][0], axh[ks][1], bh0[0], bh0[1]);
            MMA_BF16(acc[1][1], axh[ks][1], bh0[2], bh0[3]);
            MMA_BF16(acc[1][2], axh[ks][1], bh1[0], bh1[1]);
            MMA_BF16(acc[1][3], axh[ks][1], bh1[2], bh1[3]);
            MMA_BF16(acc[0][0], al0, bh0[0], bh0[1]);
            MMA_BF16(acc[0][1], al0, bh0[2], bh0[3]);
            MMA_BF16(acc[0][2], al0, bh1[0], bh1[1]);
            MMA_BF16(acc[0][3], al0, bh1[2], bh1[3]);
            MMA_BF16(acc[1][0], al1, bh0[0], bh0[1]);
            MMA_BF16(acc[1][1], al1, bh0[2], bh0[3]);
            MMA_BF16(acc[1][2], al1, bh1[0], bh1[1]);
            MMA_BF16(acc[1][3], al1, bh1[2], bh1[3]);
        }
        // seg1 (xh.cl)
#pragma unroll
        for (int ks = 0; ks < 4; ks++) {
            uint32_t bl0[4], bl1[4];
            LDSM_X4(bl0[0], bl0[1], bl0[2], bl0[3], bB + 128 + ks * 32);
            LDSM_X4(bl1[0], bl1[1], bl1[2], bl1[3],
                    bB + 16 * ROWB + 128 + ks * 32);
            MMA_BF16(acc[0][0], axh[ks][0], bl0[0], bl0[1]);
            MMA_BF16(acc[0][1], axh[ks][0], bl0[2], bl0[3]);
            MMA_BF16(acc[0][2], axh[ks][0], bl1[0], bl1[1]);
            MMA_BF16(acc[0][3], axh[ks][0], bl1[2], bl1[3]);
            MMA_BF16(acc[1][0], axh[ks][1], bl0[0], bl0[1]);
            MMA_BF16(acc[1][1], axh[ks][1], bl0[2], bl0[3]);
            MMA_BF16(acc[1][2], axh[ks][1], bl1[0], bl1[1]);
            MMA_BF16(acc[1][3], axh[ks][1], bl1[2], bl1[3]);
        }

        // epilogue: score = esq - 2*dot, track top-2 per row-slot
        const float* es = (const float*)(smem + SM_ESQ) + nt * TN + warp_n;
#pragma unroll
        for (int ni = 0; ni < 4; ni++) {
            int cb = ni * 8 + 2 * (lane & 3);
            float2 ev = *(const float2*)(es + cb);
            int colg = nt * TN + warp_n + cb;
#pragma unroll
            for (int mi = 0; mi < 2; mi++)
#pragma unroll
                for (int h = 0; h < 2; h++) {
                    int slot = mi * 2 + h;
                    float s0 = fmaf(-2.f, acc[mi][ni][2 * h + 0], ev.x);
                    float s1 = fmaf(-2.f, acc[mi][ni][2 * h + 1], ev.y);
                    if (s0 < b1v[slot]) {
                        b2v[slot] = b1v[slot]; b1v[slot] = s0; bkv[slot] = colg;
                    } else if (s0 < b2v[slot]) b2v[slot] = s0;
                    if (s1 < b1v[slot]) {
                        b2v[slot] = b1v[slot]; b1v[slot] = s1; bkv[slot] = colg + 1;
                    } else if (s1 < b2v[slot]) b2v[slot] = s1;
                }
        }

        __syncthreads();            // all warps done reading buf (nt&1)
        if (nt + 2 < NTILES) {      // refill it with tile nt+2
            const char* gsrc = (const char*)(g_B + (size_t)(nt + 2) * TN * 128);
#pragma unroll
            for (int i = tid; i < TN * 16; i += 256) {
                int row = i >> 4, c = i & 15;
                CP_ASYNC16(sb + SM_B + (nt & 1) * BUFB + row * ROWB + c * 16,
                           gsrc + row * 256 + c * 16);
            }
            CP_COMMIT();
            CP_WAIT(1);             // tile nt+1 complete
        } else {
            CP_WAIT(0);
        }
        __syncthreads();
    }

    // -- merge 1: across the 4 lanes sharing each accumulator row ------------
#pragma unroll
    for (int slot = 0; slot < 4; slot++) {
#pragma unroll
        for (int m = 1; m <= 2; m <<= 1) {
            float o1 = __shfl_xor_sync(0xffffffffu, b1v[slot], m);
            float o2 = __shfl_xor_sync(0xffffffffu, b2v[slot], m);
            int   ok = __shfl_xor_sync(0xffffffffu, bkv[slot], m);
            float nb2 = fminf(fmaxf(b1v[slot], o1), fminf(b2v[slot], o2));
            if (o1 < b1v[slot]) { b1v[slot] = o1; bkv[slot] = ok; }
            b2v[slot] = nb2;
        }
    }

    // -- merge 2: across the two n-warp groups; B smem is dead now -----------
    float* cmb = (float*)(smem + SM_B);   // [TM][4]
    if (warp_n == 32 && (lane & 3) == 0) {
#pragma unroll
        for (int slot = 0; slot < 4; slot++) {
            int mi = slot >> 1, h = slot & 1;
            int row = warp_m + mi * 16 + h * 8 + (lane >> 2);
            cmb[row * 4 + 0] = b1v[slot];
            cmb[row * 4 + 1] = b2v[slot];
            ((int*)cmb)[row * 4 + 2] = bkv[slot];
        }
    }
    __syncthreads();
    if (warp_n == 0 && (lane & 3) == 0) {
#pragma unroll
        for (int slot = 0; slot < 4; slot++) {
            int mi = slot >> 1, h = slot & 1;
            int row = warp_m + mi * 16 + h * 8 + (lane >> 2);
            float o1 = cmb[row * 4 + 0];
            float o2 = cmb[row * 4 + 1];
            int   ok = ((int*)cmb)[row * 4 + 2];
            float m2 = fminf(fmaxf(b1v[slot], o1), fminf(b2v[slot], o2));
            int   mk = (b1v[slot] <= o1) ? bkv[slot] : ok;
            float m1 = fminf(b1v[slot], o1);
            cmb[row * 4 + 0] = m1;
            cmb[row * 4 + 1] = m2;
            ((int*)cmb)[row * 4 + 2] = mk;
        }
    }
    __syncthreads();

    // -- fused finalize: 128 threads, one point each --------------------------
    if (tid < TM) {
        float b1 = cmb[tid * 4 + 0];
        float b2 = cmb[tid * 4 + 1];
        int   bk = ((int*)cmb)[tid * 4 + 2];
        int n = n0 + tid;
        bool resc = (b2 - b1 < MARGIN);
        unsigned msk = __ballot_sync(0xffffffffu, resc);
        if (resc) {
            int ldr = __ffs(msk) - 1;
            int base = 0;
            if (lane == ldr) base = atomicAdd(&g_rcount, __popc(msk));
            base = __shfl_sync(0xffffffffu, base, ldr);
            g_rescan[base + __popc(msk & ((1u << lane) - 1u))] = n;
        } else {
            if (mode & 1) out[n] = (float)bk;
            if (mode & 2) {
                int hw = n & (HW - 1);
                float* oq = out + idx_off + (size_t)b * (ND * HW) + hw;
                const float* cb = codebook + bk * ND;
#pragma unroll
                for (int d = 0; d < ND; d++) oq[d * HW] = __ldg(&cb[d]);
            }
        }
    }
}

// ---- exact fp32 rescan for near-ties ---------------------------------------
__global__ void __launch_bounds__(256)
rescan_kernel(const float* __restrict__ laten, const float* __restrict__ codebook,
              float* __restrict__ out, int mode, int idx_off) {
    __shared__ float sx[ND];
    __shared__ float sv[256];
    __shared__ int si[256];
    int tid = threadIdx.x;
    int cnt = g_rcount;
    for (int ii = blockIdx.x; ii < cnt; ii += gridDim.x) {
        int n = g_rescan[ii];
        int b = n >> 10, hw = n & (HW - 1);
        if (tid < ND) sx[tid] = laten[(size_t)b * (ND * HW) + tid * HW + hw];
        __syncthreads();
        float best = 3.4e38f;
        int bi = 0;
        for (int k = tid; k < NK; k += 256) {
            const float4* c = (const float4*)(codebook + k * ND);
            float a0 = 0.f, a1 = 0.f, a2 = 0.f, a3 = 0.f;
#pragma unroll
            for (int i = 0; i < ND / 4; i++) {
                float4 v = c[i];
                a0 = fmaf(sx[4 * i + 0], v.x, a0);
                a1 = fmaf(sx[4 * i + 1], v.y, a1);
                a2 = fmaf(sx[4 * i + 2], v.z, a2);
                a3 = fmaf(sx[4 * i + 3], v.w, a3);
            }
            float s = fmaf(-2.f, (a0 + a1) + (a2 + a3), g_esq[k]);
            if (s < best) { best = s; bi = k; }
        }
        sv[tid] = best;
        si[tid] = bi;
        __syncthreads();
        for (int off = 128; off; off >>= 1) {
            if (tid < off) {
                float ov = sv[tid + off];
                int oi = si[tid + off];
                if (ov < sv[tid] || (ov == sv[tid] && oi < si[tid])) {
                    sv[tid] = ov;
                    si[tid] = oi;
                }
            }
            __syncthreads();
        }
        int bk = si[0];
        if ((mode & 1) && tid == 0) out[n] = (float)bk;
        if ((mode & 2) && tid < ND)
            out[idx_off + (size_t)b * (ND * HW) + tid * HW + hw] =
                codebook[bk * ND + tid];
        __syncthreads();
    }
}

// ---- host launcher ----------------------------------------------------------
extern "C" void kernel_launch(void* const* d_in, const int* in_sizes, int n_in,
                              void* d_out, int out_size) {
    const float* laten    = (const float*)d_in[0];
    const float* codebook = (const float*)d_in[1];
    float* out = (float*)d_out;

    int mode, idx_off;
    if (out_size == N_POINTS + N_QUANT) { mode = 3; idx_off = N_POINTS; }
    else if (out_size == N_QUANT)       { mode = 2; idx_off = 0;        }
    else                                { mode = 1; idx_off = 0;        }

    cudaFuncSetAttribute(gemm_argmin_kernel,
                         cudaFuncAttributeMaxDynamicSharedMemorySize, SM_SIZE);

    build_B_kernel<<<NK / 128, 128>>>(codebook);
    gemm_argmin_kernel<<<N_POINTS / TM, 256, SM_SIZE>>>(laten, codebook, out,
                                                        mode, idx_off);
    rescan_kernel<<<256, 256>>>(laten, codebook, out, mode, idx_off);
}